// round 4
// baseline (speedup 1.0000x reference)
#include <cuda_runtime.h>
#include <cstdint>
#include <math.h>

// Problem constants
#define KT    64
#define VV    50000
#define DD    128
#define BOS_T 62
#define EOS_T 63
#define NB    8192
#define LL    126

// EPS = 1e-45 rounds to the smallest fp32 denormal, bit pattern 0x00000001
#define EPS_F __uint_as_float(1u)

// Scratch (static __device__ globals; no allocation allowed)
__device__ float g_A[KT * KT];        // transition probs A[k][j] (row-major)
__device__ float g_T[VV * KT];        // logits, then emission probs, layout [w][k]
__device__ float g_Z[KT];             // per-tag log-normalizer

// ---------------------------------------------------------------------------
// Kernel 1: A = softmax(WA with col BOS = -inf) + EPS
// ---------------------------------------------------------------------------
__global__ void prep_A_kernel(const float* __restrict__ WA) {
    int k = threadIdx.x;
    if (k >= KT) return;
    float x[KT];
    float m = -INFINITY;
    #pragma unroll
    for (int j = 0; j < KT; j++) {
        float v = WA[k * KT + j];
        if (j == BOS_T) v = -INFINITY;
        x[j] = v;
        m = fmaxf(m, v);
    }
    float s = 0.f;
    #pragma unroll
    for (int j = 0; j < KT; j++) {
        float e = (j == BOS_T) ? 0.f : __expf(x[j] - m);
        x[j] = e;
        s += e;
    }
    float inv = 1.0f / s;
    #pragma unroll
    for (int j = 0; j < KT; j++) {
        g_A[k * KT + j] = x[j] * inv + EPS_F;
    }
}

// ---------------------------------------------------------------------------
// Kernel 2: raw logits  g_T[w*64 + k] = dot(ThetaB[k], E[w])
// Block: 256 threads, 16 words per block. grid = V/16 = 3125 (exact).
// ---------------------------------------------------------------------------
#define WPB 16
#define TB_STRIDE 132   // padded row stride for ThetaB tile (16B aligned, de-conflicted)

__global__ void __launch_bounds__(256) logits_kernel(const float* __restrict__ ThetaB,
                                                     const float* __restrict__ E) {
    __shared__ __align__(16) float Tbs[KT * TB_STRIDE];
    __shared__ __align__(16) float Es[WPB * DD];

    int tid = threadIdx.x;
    int wbase = blockIdx.x * WPB;

    // Load ThetaB [64][128] into padded smem
    for (int idx = tid; idx < KT * DD; idx += 256) {
        int k = idx >> 7, d = idx & 127;
        Tbs[k * TB_STRIDE + d] = ThetaB[idx];
    }
    // Load E tile [16][128]
    for (int idx = tid; idx < WPB * DD; idx += 256) {
        int wl = idx >> 7, d = idx & 127;
        Es[idx] = E[(size_t)(wbase + wl) * DD + d];
    }
    __syncthreads();

    int k  = tid & 63;
    int ws = tid >> 6;   // 0..3
    float acc0 = 0.f, acc1 = 0.f, acc2 = 0.f, acc3 = 0.f;
    #pragma unroll 8
    for (int d = 0; d < DD; d += 4) {
        float4 tb = *reinterpret_cast<const float4*>(&Tbs[k * TB_STRIDE + d]);
        float4 e0 = *reinterpret_cast<const float4*>(&Es[(ws + 0) * DD + d]);
        float4 e1 = *reinterpret_cast<const float4*>(&Es[(ws + 4) * DD + d]);
        float4 e2 = *reinterpret_cast<const float4*>(&Es[(ws + 8) * DD + d]);
        float4 e3 = *reinterpret_cast<const float4*>(&Es[(ws + 12) * DD + d]);
        acc0 += tb.x * e0.x + tb.y * e0.y + tb.z * e0.z + tb.w * e0.w;
        acc1 += tb.x * e1.x + tb.y * e1.y + tb.z * e1.z + tb.w * e1.w;
        acc2 += tb.x * e2.x + tb.y * e2.y + tb.z * e2.z + tb.w * e2.w;
        acc3 += tb.x * e3.x + tb.y * e3.y + tb.z * e3.z + tb.w * e3.w;
    }
    g_T[(size_t)(wbase + ws + 0)  * KT + k] = acc0;
    g_T[(size_t)(wbase + ws + 4)  * KT + k] = acc1;
    g_T[(size_t)(wbase + ws + 8)  * KT + k] = acc2;
    g_T[(size_t)(wbase + ws + 12) * KT + k] = acc3;
}

// ---------------------------------------------------------------------------
// Kernel 3: per-tag logsumexp over V. One block per tag.
// ---------------------------------------------------------------------------
__global__ void __launch_bounds__(256) zred_kernel() {
    int k = blockIdx.x;
    int tid = threadIdx.x;
    float m = -1e30f, s = 0.f;
    for (int w = tid; w < VV; w += 256) {
        float x = g_T[(size_t)w * KT + k];
        if (x > m) { s = s * __expf(m - x) + 1.0f; m = x; }
        else       { s += __expf(x - m); }
    }
    __shared__ float sm[256], ss[256];
    sm[tid] = m; ss[tid] = s;
    __syncthreads();
    for (int off = 128; off > 0; off >>= 1) {
        if (tid < off) {
            float m1 = sm[tid], s1 = ss[tid];
            float m2 = sm[tid + off], s2 = ss[tid + off];
            float M = fmaxf(m1, m2);
            sm[tid] = M;
            ss[tid] = s1 * __expf(m1 - M) + s2 * __expf(m2 - M);
        }
        __syncthreads();
    }
    if (tid == 0) g_Z[k] = sm[0] + __logf(ss[0]);
}

// ---------------------------------------------------------------------------
// Kernel 4: T[w][k] = exp(logit - Z_k) for interior tags, EPS for BOS/EOS rows
// ---------------------------------------------------------------------------
__global__ void __launch_bounds__(256) bprob_kernel() {
    int idx = blockIdx.x * 256 + threadIdx.x;
    if (idx >= VV * KT) return;
    int k = idx & 63;
    float v;
    if (k >= BOS_T) {
        v = EPS_F;
    } else {
        v = __expf(g_T[idx] - g_Z[k]);
    }
    g_T[idx] = v;
}

// ---------------------------------------------------------------------------
// Kernel 5: scaled linear-space forward recursion.
// 4 threads per sentence; thread q owns output tags [q*16, q*16+16).
// alpha shared within the 4-lane group via shfl(width=4).
// A in smem fp32; inner matvec uses packed fma.rn.f32x2.
// ---------------------------------------------------------------------------
__device__ __forceinline__ void fma2(unsigned long long& d,
                                     unsigned long long a,
                                     unsigned long long b) {
    asm("fma.rn.f32x2 %0, %1, %2, %0;" : "+l"(d) : "l"(a), "l"(b));
}

__device__ __forceinline__ unsigned long long pack2(float a) {
    unsigned long long r;
    asm("mov.b64 %0, {%1, %1};" : "=l"(r) : "r"(__float_as_uint(a)));
    return r;
}

#define FWD_GRID 148

__global__ void __launch_bounds__(256) forward_kernel(const int* __restrict__ words,
                                                      const float* __restrict__ Btab,
                                                      float* __restrict__ out) {
    __shared__ __align__(16) float As[KT * KT];
    for (int i = threadIdx.x; i < KT * KT; i += blockDim.x) As[i] = g_A[i];
    __syncthreads();

    int c = blockIdx.x;
    int start = (c * NB) / FWD_GRID;
    int end   = ((c + 1) * NB) / FWD_GRID;
    int slot  = threadIdx.x >> 2;
    int q     = threadIdx.x & 3;
    int b     = start + slot;
    if (b >= end) return;                       // whole 4-lane groups exit together

    unsigned gmask = 0xFu << (threadIdx.x & 28);

    float alpha[16];
    #pragma unroll
    for (int i = 0; i < 16; i++) alpha[i] = 0.f;
    if (q == 3) alpha[BOS_T - 48] = 1.0f;       // tag 62 = q3, idx 14

    const int* wp = words + (size_t)b * LL;
    int w0 = wp[0];
    const float4* Tr = reinterpret_cast<const float4*>(Btab + (size_t)w0 * KT + q * 16);
    float4 em0 = Tr[0], em1 = Tr[1], em2 = Tr[2], em3 = Tr[3];
    int wnext = wp[1];

    float logscale = 0.f;
    const unsigned long long* As2 = reinterpret_cast<const unsigned long long*>(As);

    for (int t = 0; t < LL; t++) {
        // prefetch next step's emission (consumed at the END of next iteration)
        const float4* Tn = reinterpret_cast<const float4*>(Btab + (size_t)wnext * KT + q * 16);
        float4 n0 = Tn[0], n1 = Tn[1], n2 = Tn[2], n3 = Tn[3];
        int wn2 = (t + 2 < LL) ? wp[t + 2] : 0;

        // matvec: acc[j] = sum_k alpha[k] * A[k][j], packed 2-wide
        unsigned long long acc[8];
        #pragma unroll
        for (int i = 0; i < 8; i++) acc[i] = 0ull;

        #pragma unroll
        for (int k = 0; k < KT; k++) {
            float a = __shfl_sync(gmask, alpha[k & 15], k >> 4, 4);
            unsigned long long a2 = pack2(a);
            const ulonglong2* Ar =
                reinterpret_cast<const ulonglong2*>(As2 + k * 32 + q * 8);
            ulonglong2 p0 = Ar[0];
            ulonglong2 p1 = Ar[1];
            ulonglong2 p2 = Ar[2];
            ulonglong2 p3 = Ar[3];
            fma2(acc[0], a2, p0.x); fma2(acc[1], a2, p0.y);
            fma2(acc[2], a2, p1.x); fma2(acc[3], a2, p1.y);
            fma2(acc[4], a2, p2.x); fma2(acc[5], a2, p2.y);
            fma2(acc[6], a2, p3.x); fma2(acc[7], a2, p3.y);
        }

        // unpack, apply emission, rescale
        float nv[16];
        #pragma unroll
        for (int i = 0; i < 8; i++) {
            nv[2 * i + 0] = __uint_as_float((unsigned)(acc[i] & 0xffffffffull));
            nv[2 * i + 1] = __uint_as_float((unsigned)(acc[i] >> 32));
        }
        nv[0]  *= em0.x; nv[1]  *= em0.y; nv[2]  *= em0.z; nv[3]  *= em0.w;
        nv[4]  *= em1.x; nv[5]  *= em1.y; nv[6]  *= em1.z; nv[7]  *= em1.w;
        nv[8]  *= em2.x; nv[9]  *= em2.y; nv[10] *= em2.z; nv[11] *= em2.w;
        nv[12] *= em3.x; nv[13] *= em3.y; nv[14] *= em3.z; nv[15] *= em3.w;

        float m = nv[0];
        #pragma unroll
        for (int i = 1; i < 16; i++) m = fmaxf(m, nv[i]);
        m = fmaxf(m, __shfl_xor_sync(gmask, m, 1, 4));
        m = fmaxf(m, __shfl_xor_sync(gmask, m, 2, 4));

        float r = 1.0f / m;
        #pragma unroll
        for (int i = 0; i < 16; i++) alpha[i] = nv[i] * r;
        logscale += __logf(m);

        em0 = n0; em1 = n1; em2 = n2; em3 = n3;
        wnext = wn2;
    }

    // final transition into EOS (no emission)
    float s = 0.f;
    #pragma unroll
    for (int i = 0; i < 16; i++) s += alpha[i] * As[(q * 16 + i) * KT + EOS_T];
    s += __shfl_xor_sync(gmask, s, 1, 4);
    s += __shfl_xor_sync(gmask, s, 2, 4);
    if (q == 0) out[b] = logscale + __logf(s);
}

// ---------------------------------------------------------------------------
// Launch
// ---------------------------------------------------------------------------
extern "C" void kernel_launch(void* const* d_in, const int* in_sizes, int n_in,
                              void* d_out, int out_size) {
    const int*   words  = nullptr;
    const float* ThetaB = nullptr;
    const float* WA     = nullptr;
    const float* E      = nullptr;
    for (int i = 0; i < n_in; i++) {
        switch (in_sizes[i]) {
            case NB * LL:  words  = (const int*)d_in[i];   break;  // 1032192
            case KT * DD:  ThetaB = (const float*)d_in[i]; break;  // 8192
            case KT * KT:  WA     = (const float*)d_in[i]; break;  // 4096
            case VV * DD:  E      = (const float*)d_in[i]; break;  // 6400000
            default: break;
        }
    }
    float* out = (float*)d_out;

    prep_A_kernel<<<1, 64>>>(WA);
    logits_kernel<<<VV / WPB, 256>>>(ThetaB, E);
    zred_kernel<<<KT, 256>>>();
    bprob_kernel<<<(VV * KT + 255) / 256, 256>>>();

    // device pointer to g_T via cudaGetSymbolAddress is not graph-unsafe, but
    // simplest is to pass the symbol through a launch that references it:
    float* Tptr = nullptr;
    cudaGetSymbolAddress((void**)&Tptr, g_T);
    forward_kernel<<<FWD_GRID, 256>>>(words, Tptr, out);
}

// round 5
// speedup vs baseline: 2.7600x; 2.7600x over previous
#include <cuda_runtime.h>
#include <cstdint>
#include <math.h>

// Problem constants
#define KT    64
#define VV    50000
#define DD    128
#define BOS_T 62
#define EOS_T 63
#define NB    8192
#define LL    126

// EPS = 1e-45 rounds to the smallest fp32 denormal, bit pattern 0x00000001
#define EPS_F __uint_as_float(1u)

// Scratch (static __device__ globals; no allocation allowed)
__device__ float g_A[KT * KT];        // transition probs A[k][j] (row-major)
__device__ float g_T[VV * KT];        // logits, then emission probs, layout [w][k]
__device__ float g_Z[KT];             // per-tag log-normalizer
#define ZBLK 128
__device__ float g_pm[ZBLK * KT];     // partial max per (block, tag)
__device__ float g_ps[ZBLK * KT];     // partial sum per (block, tag)

// ---------------------------------------------------------------------------
// packed f32x2 helpers
// ---------------------------------------------------------------------------
__device__ __forceinline__ void fma2(unsigned long long& d,
                                     unsigned long long a,
                                     unsigned long long b) {
    asm("fma.rn.f32x2 %0, %1, %2, %0;" : "+l"(d) : "l"(a), "l"(b));
}
__device__ __forceinline__ unsigned long long pack2(float a) {
    unsigned long long r;
    asm("mov.b64 %0, {%1, %1};" : "=l"(r) : "r"(__float_as_uint(a)));
    return r;
}
__device__ __forceinline__ float lo64(unsigned long long v) {
    return __uint_as_float((unsigned)(v & 0xffffffffull));
}
__device__ __forceinline__ float hi64(unsigned long long v) {
    return __uint_as_float((unsigned)(v >> 32));
}

// ---------------------------------------------------------------------------
// Kernel 1: A = softmax(WA with col BOS = -inf) + EPS
// ---------------------------------------------------------------------------
__global__ void prep_A_kernel(const float* __restrict__ WA) {
    int k = threadIdx.x;
    if (k >= KT) return;
    float x[KT];
    float m = -INFINITY;
    #pragma unroll
    for (int j = 0; j < KT; j++) {
        float v = WA[k * KT + j];
        if (j == BOS_T) v = -INFINITY;
        x[j] = v;
        m = fmaxf(m, v);
    }
    float s = 0.f;
    #pragma unroll
    for (int j = 0; j < KT; j++) {
        float e = (j == BOS_T) ? 0.f : __expf(x[j] - m);
        x[j] = e;
        s += e;
    }
    float inv = 1.0f / s;
    #pragma unroll
    for (int j = 0; j < KT; j++) {
        g_A[k * KT + j] = x[j] * inv + EPS_F;
    }
}

// ---------------------------------------------------------------------------
// Kernel 2: raw logits  g_T[w*64 + k] = dot(ThetaB[k], E[w]), packed f32x2
// ---------------------------------------------------------------------------
#define WPB 16
#define TB_STRIDE 132   // padded row stride (528B = 33*16, 16B-aligned rows)

__global__ void __launch_bounds__(256) logits_kernel(const float* __restrict__ ThetaB,
                                                     const float* __restrict__ E) {
    __shared__ __align__(16) float Tbs[KT * TB_STRIDE];
    __shared__ __align__(16) float Es[WPB * DD];

    int tid = threadIdx.x;
    int wbase = blockIdx.x * WPB;

    for (int idx = tid; idx < KT * DD; idx += 256) {
        int k = idx >> 7, d = idx & 127;
        Tbs[k * TB_STRIDE + d] = ThetaB[idx];
    }
    for (int idx = tid; idx < WPB * DD; idx += 256) {
        Es[idx] = E[(size_t)wbase * DD + idx];
    }
    __syncthreads();

    int k  = tid & 63;
    int ws = tid >> 6;   // 0..3
    unsigned long long a0 = 0, a1 = 0, a2 = 0, a3 = 0;
    #pragma unroll 8
    for (int d = 0; d < DD; d += 4) {
        ulonglong2 tb = *reinterpret_cast<const ulonglong2*>(&Tbs[k * TB_STRIDE + d]);
        ulonglong2 e0 = *reinterpret_cast<const ulonglong2*>(&Es[(ws + 0) * DD + d]);
        ulonglong2 e1 = *reinterpret_cast<const ulonglong2*>(&Es[(ws + 4) * DD + d]);
        ulonglong2 e2 = *reinterpret_cast<const ulonglong2*>(&Es[(ws + 8) * DD + d]);
        ulonglong2 e3 = *reinterpret_cast<const ulonglong2*>(&Es[(ws + 12) * DD + d]);
        fma2(a0, tb.x, e0.x); fma2(a0, tb.y, e0.y);
        fma2(a1, tb.x, e1.x); fma2(a1, tb.y, e1.y);
        fma2(a2, tb.x, e2.x); fma2(a2, tb.y, e2.y);
        fma2(a3, tb.x, e3.x); fma2(a3, tb.y, e3.y);
    }
    g_T[(size_t)(wbase + ws + 0)  * KT + k] = lo64(a0) + hi64(a0);
    g_T[(size_t)(wbase + ws + 4)  * KT + k] = lo64(a1) + hi64(a1);
    g_T[(size_t)(wbase + ws + 8)  * KT + k] = lo64(a2) + hi64(a2);
    g_T[(size_t)(wbase + ws + 12) * KT + k] = lo64(a3) + hi64(a3);
}

// ---------------------------------------------------------------------------
// Kernel 3a: coalesced partial logsumexp per tag over row blocks
// ---------------------------------------------------------------------------
__global__ void __launch_bounds__(256) zred1_kernel() {
    int r0 = (int)(((long long)blockIdx.x * VV) / ZBLK);
    int r1 = (int)(((long long)(blockIdx.x + 1) * VV) / ZBLK);
    int tid = threadIdx.x;
    int k = tid & 63, g = tid >> 6;   // 4 row-groups of 64 tags
    float m = -1e30f, s = 0.f;
    for (int r = r0 + g; r < r1; r += 4) {
        float x = g_T[(size_t)r * KT + k];
        if (x > m) { s = s * __expf(m - x) + 1.0f; m = x; }
        else       { s += __expf(x - m); }
    }
    __shared__ float sm[256], ss[256];
    sm[tid] = m; ss[tid] = s;
    __syncthreads();
    if (g == 0) {
        #pragma unroll
        for (int o = 1; o < 4; o++) {
            float m2 = sm[tid + o * 64], s2 = ss[tid + o * 64];
            if (m2 > m) { s = s * __expf(m - m2) + s2; m = m2; }
            else        { s += s2 * __expf(m2 - m); }
        }
        g_pm[blockIdx.x * KT + k] = m;
        g_ps[blockIdx.x * KT + k] = s;
    }
}

// Kernel 3b: reduce partials -> g_Z
__global__ void zred2_kernel() {
    int k = threadIdx.x;
    if (k >= KT) return;
    float m = -1e30f, s = 0.f;
    for (int b = 0; b < ZBLK; b++) {
        float m2 = g_pm[b * KT + k], s2 = g_ps[b * KT + k];
        if (m2 > m) { s = s * __expf(m - m2) + s2; m = m2; }
        else        { s += s2 * __expf(m2 - m); }
    }
    g_Z[k] = m + __logf(s);
}

// ---------------------------------------------------------------------------
// Kernel 4: T[w][k] = exp(logit - Z_k) interior tags, EPS for BOS/EOS (float4)
// ---------------------------------------------------------------------------
__global__ void __launch_bounds__(256) bprob_kernel() {
    __shared__ float Zs[KT];
    if (threadIdx.x < KT) Zs[threadIdx.x] = g_Z[threadIdx.x];
    __syncthreads();
    size_t q = (size_t)blockIdx.x * 256 + threadIdx.x;   // quad index
    if (q >= (size_t)VV * (KT / 4)) return;
    int k0 = (int)((q * 4) & 63);
    float4 v = *reinterpret_cast<const float4*>(&g_T[q * 4]);
    if (k0 == 60) {
        v.x = __expf(v.x - Zs[60]);
        v.y = __expf(v.y - Zs[61]);
        v.z = EPS_F;
        v.w = EPS_F;
    } else {
        v.x = __expf(v.x - Zs[k0 + 0]);
        v.y = __expf(v.y - Zs[k0 + 1]);
        v.z = __expf(v.z - Zs[k0 + 2]);
        v.w = __expf(v.w - Zs[k0 + 3]);
    }
    *reinterpret_cast<float4*>(&g_T[q * 4]) = v;
}

// ---------------------------------------------------------------------------
// Kernel 5: forward recursion. A register-resident (2 cols/lane as f32x2),
// alpha in smem pre-duplicated {a,a}; one warp = 7 sentences, all 64 tags.
// ---------------------------------------------------------------------------
#define FW_CTAS  148
#define FW_WARPS 8
#define FW_SENT  7

__global__ void __launch_bounds__(256) forward_kernel(const int* __restrict__ words,
                                                      const float* __restrict__ Btab,
                                                      float* __restrict__ out) {
    __shared__ __align__(16) float As[KT * KT];                              // 16 KB
    __shared__ __align__(16) unsigned long long Al[FW_WARPS][FW_SENT][KT];   // 28 KB

    int tid = threadIdx.x;
    for (int i = tid; i < KT * KT; i += 256) As[i] = g_A[i];
    __syncthreads();

    int wid = tid >> 5, lane = tid & 31;

    // A columns (2*lane, 2*lane+1), all 64 rows, packed in registers
    unsigned long long Areg[KT];
    #pragma unroll
    for (int k = 0; k < KT; k++)
        Areg[k] = *reinterpret_cast<const unsigned long long*>(&As[k * KT + 2 * lane]);

    int gw = blockIdx.x * FW_WARPS + wid;
    int base = gw * FW_SENT;

    int bidx[FW_SENT];
    #pragma unroll
    for (int s = 0; s < FW_SENT; s++) bidx[s] = min(base + s, NB - 1);

    // init alpha (duplicated pairs): all zero, one-hot at BOS tag 62
    #pragma unroll
    for (int s = 0; s < FW_SENT; s++) {
        Al[wid][s][lane]      = 0ull;
        Al[wid][s][lane + 32] = 0ull;
    }
    __syncwarp();
    if (lane < FW_SENT) Al[wid][lane][BOS_T] = 0x3f8000003f800000ull;  // {1.f,1.f}
    __syncwarp();

    const int* wp[FW_SENT];
    float2 em[FW_SENT];
    int wn[FW_SENT];
    float lsc[FW_SENT];
    #pragma unroll
    for (int s = 0; s < FW_SENT; s++) {
        wp[s] = words + (size_t)bidx[s] * LL;
        int w0 = wp[s][0];
        em[s] = *reinterpret_cast<const float2*>(Btab + (size_t)w0 * KT + 2 * lane);
        wn[s] = wp[s][1];
        lsc[s] = 0.f;
    }

    for (int t = 0; t < LL; t++) {
        // prefetch next step's emission + the word after
        float2 emn[FW_SENT]; int wn2[FW_SENT];
        #pragma unroll
        for (int s = 0; s < FW_SENT; s++) {
            emn[s] = *reinterpret_cast<const float2*>(Btab + (size_t)wn[s] * KT + 2 * lane);
            wn2[s] = (t + 2 < LL) ? wp[s][t + 2] : 0;
        }

        // matvec: acc(cols 2l,2l+1) = sum_k alpha[k] * A[k][2l..2l+1]
        unsigned long long acc[FW_SENT];
        #pragma unroll
        for (int s = 0; s < FW_SENT; s++) acc[s] = 0ull;
        #pragma unroll
        for (int k = 0; k < KT; k += 2) {
            #pragma unroll
            for (int s = 0; s < FW_SENT; s++) {
                ulonglong2 a2 = *reinterpret_cast<const ulonglong2*>(&Al[wid][s][k]);
                fma2(acc[s], a2.x, Areg[k]);
                fma2(acc[s], a2.y, Areg[k + 1]);
            }
        }

        // emission, per-sentence warp max, rescale, write duplicated alpha
        float m[FW_SENT], n0[FW_SENT], n1[FW_SENT];
        #pragma unroll
        for (int s = 0; s < FW_SENT; s++) {
            n0[s] = lo64(acc[s]) * em[s].x;
            n1[s] = hi64(acc[s]) * em[s].y;
            m[s]  = fmaxf(n0[s], n1[s]);
        }
        #pragma unroll
        for (int off = 16; off > 0; off >>= 1) {
            #pragma unroll
            for (int s = 0; s < FW_SENT; s++)
                m[s] = fmaxf(m[s], __shfl_xor_sync(0xffffffffu, m[s], off));
        }
        #pragma unroll
        for (int s = 0; s < FW_SENT; s++) {
            float r = __fdividef(1.0f, m[s]);
            ulonglong2 st;
            st.x = pack2(n0[s] * r);
            st.y = pack2(n1[s] * r);
            *reinterpret_cast<ulonglong2*>(&Al[wid][s][2 * lane]) = st;
            lsc[s] += __logf(m[s]);
            em[s] = emn[s];
            wn[s] = wn2[s];
        }
        __syncwarp();
    }

    // final transition into EOS (col 63, held by lane 31 high half)
    unsigned long long facc[FW_SENT];
    #pragma unroll
    for (int s = 0; s < FW_SENT; s++) facc[s] = 0ull;
    #pragma unroll
    for (int k = 0; k < KT; k += 2) {
        #pragma unroll
        for (int s = 0; s < FW_SENT; s++) {
            ulonglong2 a2 = *reinterpret_cast<const ulonglong2*>(&Al[wid][s][k]);
            fma2(facc[s], a2.x, Areg[k]);
            fma2(facc[s], a2.y, Areg[k + 1]);
        }
    }
    if (lane == 31) {
        #pragma unroll
        for (int s = 0; s < FW_SENT; s++) {
            int b = base + s;
            if (b < NB) out[b] = lsc[s] + __logf(hi64(facc[s]));
        }
    }
}

// ---------------------------------------------------------------------------
// Launch
// ---------------------------------------------------------------------------
extern "C" void kernel_launch(void* const* d_in, const int* in_sizes, int n_in,
                              void* d_out, int out_size) {
    const int*   words  = nullptr;
    const float* ThetaB = nullptr;
    const float* WA     = nullptr;
    const float* E      = nullptr;
    for (int i = 0; i < n_in; i++) {
        switch (in_sizes[i]) {
            case NB * LL:  words  = (const int*)d_in[i];   break;  // 1032192
            case KT * DD:  ThetaB = (const float*)d_in[i]; break;  // 8192
            case KT * KT:  WA     = (const float*)d_in[i]; break;  // 4096
            case VV * DD:  E      = (const float*)d_in[i]; break;  // 6400000
            default: break;
        }
    }
    float* out = (float*)d_out;

    prep_A_kernel<<<1, 64>>>(WA);
    logits_kernel<<<VV / WPB, 256>>>(ThetaB, E);
    zred1_kernel<<<ZBLK, 256>>>();
    zred2_kernel<<<1, 64>>>();
    bprob_kernel<<<(VV * (KT / 4) + 255) / 256, 256>>>();

    float* Tptr = nullptr;
    cudaGetSymbolAddress((void**)&Tptr, g_T);
    forward_kernel<<<FW_CTAS, 256>>>(words, Tptr, out);
}

// round 6
// speedup vs baseline: 2.9037x; 1.0521x over previous
#include <cuda_runtime.h>
#include <cstdint>
#include <math.h>

// Problem constants
#define KT    64
#define VV    50000
#define DD    128
#define BOS_T 62
#define EOS_T 63
#define NB    8192
#define LL    126

// EPS = 1e-45 rounds to the smallest fp32 denormal, bit pattern 0x00000001
#define EPS_F __uint_as_float(1u)

// log(V) and 126*log(V) (double-evaluated, rounded once to fp32)
#define LOGV_F   10.819778284410284f
#define CORR_F   1363.2920638356958f

// Scratch (static __device__ globals; no allocation allowed)
__device__ float g_A[KT * KT];        // transition probs A[k][j] (row-major)
__device__ float g_T[VV * KT];        // logits, then V-scaled emission probs [w][k]
__device__ float g_Z[KT];             // per-tag log-normalizer minus log(V)
#define ZBLK 128
__device__ float g_pm[ZBLK * KT];     // partial max per (block, tag)
__device__ float g_ps[ZBLK * KT];     // partial sum per (block, tag)

// ---------------------------------------------------------------------------
// packed f32x2 helpers
// ---------------------------------------------------------------------------
__device__ __forceinline__ void fma2(unsigned long long& d,
                                     unsigned long long a,
                                     unsigned long long b) {
    asm("fma.rn.f32x2 %0, %1, %2, %0;" : "+l"(d) : "l"(a), "l"(b));
}
__device__ __forceinline__ unsigned long long pack2(float a) {
    unsigned long long r;
    asm("mov.b64 %0, {%1, %1};" : "=l"(r) : "r"(__float_as_uint(a)));
    return r;
}
__device__ __forceinline__ float lo64(unsigned long long v) {
    return __uint_as_float((unsigned)(v & 0xffffffffull));
}
__device__ __forceinline__ float hi64(unsigned long long v) {
    return __uint_as_float((unsigned)(v >> 32));
}

// ---------------------------------------------------------------------------
// Kernel 1: A = softmax(WA with col BOS = -inf) + EPS
// ---------------------------------------------------------------------------
__global__ void prep_A_kernel(const float* __restrict__ WA) {
    int k = threadIdx.x;
    if (k >= KT) return;
    float x[KT];
    float m = -INFINITY;
    #pragma unroll
    for (int j = 0; j < KT; j++) {
        float v = WA[k * KT + j];
        if (j == BOS_T) v = -INFINITY;
        x[j] = v;
        m = fmaxf(m, v);
    }
    float s = 0.f;
    #pragma unroll
    for (int j = 0; j < KT; j++) {
        float e = (j == BOS_T) ? 0.f : __expf(x[j] - m);
        x[j] = e;
        s += e;
    }
    float inv = 1.0f / s;
    #pragma unroll
    for (int j = 0; j < KT; j++) {
        g_A[k * KT + j] = x[j] * inv + EPS_F;
    }
}

// ---------------------------------------------------------------------------
// Kernel 2: raw logits  g_T[w*64 + k] = dot(ThetaB[k], E[w]), packed f32x2
// ---------------------------------------------------------------------------
#define WPB 16
#define TB_STRIDE 132   // padded row stride (16B-aligned rows)

__global__ void __launch_bounds__(256) logits_kernel(const float* __restrict__ ThetaB,
                                                     const float* __restrict__ E) {
    __shared__ __align__(16) float Tbs[KT * TB_STRIDE];
    __shared__ __align__(16) float Es[WPB * DD];

    int tid = threadIdx.x;
    int wbase = blockIdx.x * WPB;

    for (int idx = tid; idx < KT * DD; idx += 256) {
        int k = idx >> 7, d = idx & 127;
        Tbs[k * TB_STRIDE + d] = ThetaB[idx];
    }
    for (int idx = tid; idx < WPB * DD; idx += 256) {
        Es[idx] = E[(size_t)wbase * DD + idx];
    }
    __syncthreads();

    int k  = tid & 63;
    int ws = tid >> 6;   // 0..3
    unsigned long long a0 = 0, a1 = 0, a2 = 0, a3 = 0;
    #pragma unroll 8
    for (int d = 0; d < DD; d += 4) {
        ulonglong2 tb = *reinterpret_cast<const ulonglong2*>(&Tbs[k * TB_STRIDE + d]);
        ulonglong2 e0 = *reinterpret_cast<const ulonglong2*>(&Es[(ws + 0) * DD + d]);
        ulonglong2 e1 = *reinterpret_cast<const ulonglong2*>(&Es[(ws + 4) * DD + d]);
        ulonglong2 e2 = *reinterpret_cast<const ulonglong2*>(&Es[(ws + 8) * DD + d]);
        ulonglong2 e3 = *reinterpret_cast<const ulonglong2*>(&Es[(ws + 12) * DD + d]);
        fma2(a0, tb.x, e0.x); fma2(a0, tb.y, e0.y);
        fma2(a1, tb.x, e1.x); fma2(a1, tb.y, e1.y);
        fma2(a2, tb.x, e2.x); fma2(a2, tb.y, e2.y);
        fma2(a3, tb.x, e3.x); fma2(a3, tb.y, e3.y);
    }
    g_T[(size_t)(wbase + ws + 0)  * KT + k] = lo64(a0) + hi64(a0);
    g_T[(size_t)(wbase + ws + 4)  * KT + k] = lo64(a1) + hi64(a1);
    g_T[(size_t)(wbase + ws + 8)  * KT + k] = lo64(a2) + hi64(a2);
    g_T[(size_t)(wbase + ws + 12) * KT + k] = lo64(a3) + hi64(a3);
}

// ---------------------------------------------------------------------------
// Kernel 3a: coalesced partial logsumexp per tag over row blocks
// ---------------------------------------------------------------------------
__global__ void __launch_bounds__(256) zred1_kernel() {
    int r0 = (int)(((long long)blockIdx.x * VV) / ZBLK);
    int r1 = (int)(((long long)(blockIdx.x + 1) * VV) / ZBLK);
    int tid = threadIdx.x;
    int k = tid & 63, g = tid >> 6;   // 4 row-groups of 64 tags
    float m = -1e30f, s = 0.f;
    for (int r = r0 + g; r < r1; r += 4) {
        float x = g_T[(size_t)r * KT + k];
        if (x > m) { s = s * __expf(m - x) + 1.0f; m = x; }
        else       { s += __expf(x - m); }
    }
    __shared__ float sm[256], ss[256];
    sm[tid] = m; ss[tid] = s;
    __syncthreads();
    if (g == 0) {
        #pragma unroll
        for (int o = 1; o < 4; o++) {
            float m2 = sm[tid + o * 64], s2 = ss[tid + o * 64];
            if (m2 > m) { s = s * __expf(m - m2) + s2; m = m2; }
            else        { s += s2 * __expf(m2 - m); }
        }
        g_pm[blockIdx.x * KT + k] = m;
        g_ps[blockIdx.x * KT + k] = s;
    }
}

// Kernel 3b: reduce partials -> g_Z (parallel; folds -log(V) into Z)
__global__ void __launch_bounds__(256) zred2_kernel() {
    int tid = threadIdx.x;
    int k = tid & 63, g = tid >> 6;   // 4 groups of 32 partials each
    float m = -1e30f, s = 0.f;
    for (int b = g; b < ZBLK; b += 4) {
        float m2 = g_pm[b * KT + k], s2 = g_ps[b * KT + k];
        if (m2 > m) { s = s * __expf(m - m2) + s2; m = m2; }
        else        { s += s2 * __expf(m2 - m); }
    }
    __shared__ float sm[256], ss[256];
    sm[tid] = m; ss[tid] = s;
    __syncthreads();
    if (g == 0) {
        #pragma unroll
        for (int o = 1; o < 4; o++) {
            float m2 = sm[tid + o * 64], s2 = ss[tid + o * 64];
            if (m2 > m) { s = s * __expf(m - m2) + s2; m = m2; }
            else        { s += s2 * __expf(m2 - m); }
        }
        g_Z[k] = m + __logf(s) - LOGV_F;   // Z' = Z - log(V) => em = V*B
    }
}

// ---------------------------------------------------------------------------
// Kernel 4: T[w][k] = exp(logit - Z'_k) = V*B for interior tags, EPS BOS/EOS
// ---------------------------------------------------------------------------
__global__ void __launch_bounds__(256) bprob_kernel() {
    __shared__ float Zs[KT];
    if (threadIdx.x < KT) Zs[threadIdx.x] = g_Z[threadIdx.x];
    __syncthreads();
    size_t q = (size_t)blockIdx.x * 256 + threadIdx.x;   // quad index
    if (q >= (size_t)VV * (KT / 4)) return;
    int k0 = (int)((q * 4) & 63);
    float4 v = *reinterpret_cast<const float4*>(&g_T[q * 4]);
    if (k0 == 60) {
        v.x = __expf(v.x - Zs[60]);
        v.y = __expf(v.y - Zs[61]);
        v.z = EPS_F;
        v.w = EPS_F;
    } else {
        v.x = __expf(v.x - Zs[k0 + 0]);
        v.y = __expf(v.y - Zs[k0 + 1]);
        v.z = __expf(v.z - Zs[k0 + 2]);
        v.w = __expf(v.w - Zs[k0 + 3]);
    }
    *reinterpret_cast<float4*>(&g_T[q * 4]) = v;
}

// ---------------------------------------------------------------------------
// Kernel 5: forward recursion, V-scaled emissions, rescale every 16th step.
// A register-resident (2 cols/lane as f32x2), alpha in smem as {a,a} pairs;
// one warp = 7 sentences, all 64 tags.
// ---------------------------------------------------------------------------
#define FW_CTAS  148
#define FW_WARPS 8
#define FW_SENT  7
#define RS_MASK  15

__global__ void __launch_bounds__(256) forward_kernel(const int* __restrict__ words,
                                                      const float* __restrict__ Btab,
                                                      float* __restrict__ out) {
    __shared__ __align__(16) float As[KT * KT];                              // 16 KB
    __shared__ __align__(16) unsigned long long Al[FW_WARPS][FW_SENT][KT];   // 28 KB

    int tid = threadIdx.x;
    for (int i = tid; i < KT * KT; i += 256) As[i] = g_A[i];
    __syncthreads();

    int wid = tid >> 5, lane = tid & 31;

    // A columns (2*lane, 2*lane+1), all 64 rows, packed in registers
    unsigned long long Areg[KT];
    #pragma unroll
    for (int k = 0; k < KT; k++)
        Areg[k] = *reinterpret_cast<const unsigned long long*>(&As[k * KT + 2 * lane]);

    int gw = blockIdx.x * FW_WARPS + wid;
    int base = gw * FW_SENT;

    int bidx[FW_SENT];
    #pragma unroll
    for (int s = 0; s < FW_SENT; s++) bidx[s] = min(base + s, NB - 1);

    // init alpha (duplicated pairs): all zero, one-hot at BOS tag 62
    #pragma unroll
    for (int s = 0; s < FW_SENT; s++) {
        Al[wid][s][lane]      = 0ull;
        Al[wid][s][lane + 32] = 0ull;
    }
    __syncwarp();
    if (lane < FW_SENT) Al[wid][lane][BOS_T] = 0x3f8000003f800000ull;  // {1.f,1.f}
    __syncwarp();

    const int* wp[FW_SENT];
    float2 em[FW_SENT];
    int wn[FW_SENT];
    float lsc[FW_SENT];
    #pragma unroll
    for (int s = 0; s < FW_SENT; s++) {
        wp[s] = words + (size_t)bidx[s] * LL;
        int w0 = wp[s][0];
        em[s] = *reinterpret_cast<const float2*>(Btab + (size_t)w0 * KT + 2 * lane);
        wn[s] = wp[s][1];
        lsc[s] = 0.f;
    }

    for (int t = 0; t < LL; t++) {
        // prefetch next step's emission + the word after
        float2 emn[FW_SENT]; int wn2[FW_SENT];
        #pragma unroll
        for (int s = 0; s < FW_SENT; s++) {
            emn[s] = *reinterpret_cast<const float2*>(Btab + (size_t)wn[s] * KT + 2 * lane);
            wn2[s] = (t + 2 < LL) ? wp[s][t + 2] : 0;
        }

        // matvec: acc(cols 2l,2l+1) = sum_k alpha[k] * A[k][2l..2l+1]
        unsigned long long acc[FW_SENT];
        #pragma unroll
        for (int s = 0; s < FW_SENT; s++) acc[s] = 0ull;
        #pragma unroll
        for (int k = 0; k < KT; k += 2) {
            #pragma unroll
            for (int s = 0; s < FW_SENT; s++) {
                ulonglong2 a2 = *reinterpret_cast<const ulonglong2*>(&Al[wid][s][k]);
                fma2(acc[s], a2.x, Areg[k]);
                fma2(acc[s], a2.y, Areg[k + 1]);
            }
        }

        if ((t & RS_MASK) == RS_MASK) {
            // full rescale: per-sentence warp max, normalize, accumulate log
            float m[FW_SENT], n0[FW_SENT], n1[FW_SENT];
            #pragma unroll
            for (int s = 0; s < FW_SENT; s++) {
                n0[s] = lo64(acc[s]) * em[s].x;
                n1[s] = hi64(acc[s]) * em[s].y;
                m[s]  = fmaxf(n0[s], n1[s]);
            }
            #pragma unroll
            for (int off = 16; off > 0; off >>= 1) {
                #pragma unroll
                for (int s = 0; s < FW_SENT; s++)
                    m[s] = fmaxf(m[s], __shfl_xor_sync(0xffffffffu, m[s], off));
            }
            #pragma unroll
            for (int s = 0; s < FW_SENT; s++) {
                float r = __fdividef(1.0f, m[s]);
                ulonglong2 st;
                st.x = pack2(n0[s] * r);
                st.y = pack2(n1[s] * r);
                *reinterpret_cast<ulonglong2*>(&Al[wid][s][2 * lane]) = st;
                lsc[s] += __logf(m[s]);
            }
        } else {
            // fast path: apply emission, store (no rescale — em ~= 1 keeps range)
            #pragma unroll
            for (int s = 0; s < FW_SENT; s++) {
                ulonglong2 st;
                st.x = pack2(lo64(acc[s]) * em[s].x);
                st.y = pack2(hi64(acc[s]) * em[s].y);
                *reinterpret_cast<ulonglong2*>(&Al[wid][s][2 * lane]) = st;
            }
        }

        #pragma unroll
        for (int s = 0; s < FW_SENT; s++) { em[s] = emn[s]; wn[s] = wn2[s]; }
        __syncwarp();
    }

    // final transition into EOS (col 63, held by lane 31 high half)
    unsigned long long facc[FW_SENT];
    #pragma unroll
    for (int s = 0; s < FW_SENT; s++) facc[s] = 0ull;
    #pragma unroll
    for (int k = 0; k < KT; k += 2) {
        #pragma unroll
        for (int s = 0; s < FW_SENT; s++) {
            ulonglong2 a2 = *reinterpret_cast<const ulonglong2*>(&Al[wid][s][k]);
            fma2(facc[s], a2.x, Areg[k]);
            fma2(facc[s], a2.y, Areg[k + 1]);
        }
    }
    if (lane == 31) {
        #pragma unroll
        for (int s = 0; s < FW_SENT; s++) {
            int b = base + s;
            if (b < NB) out[b] = lsc[s] + __logf(hi64(facc[s])) - CORR_F;
        }
    }
}

// ---------------------------------------------------------------------------
// Launch
// ---------------------------------------------------------------------------
extern "C" void kernel_launch(void* const* d_in, const int* in_sizes, int n_in,
                              void* d_out, int out_size) {
    const int*   words  = nullptr;
    const float* ThetaB = nullptr;
    const float* WA     = nullptr;
    const float* E      = nullptr;
    for (int i = 0; i < n_in; i++) {
        switch (in_sizes[i]) {
            case NB * LL:  words  = (const int*)d_in[i];   break;  // 1032192
            case KT * DD:  ThetaB = (const float*)d_in[i]; break;  // 8192
            case KT * KT:  WA     = (const float*)d_in[i]; break;  // 4096
            case VV * DD:  E      = (const float*)d_in[i]; break;  // 6400000
            default: break;
        }
    }
    float* out = (float*)d_out;

    prep_A_kernel<<<1, 64>>>(WA);
    logits_kernel<<<VV / WPB, 256>>>(ThetaB, E);
    zred1_kernel<<<ZBLK, 256>>>();
    zred2_kernel<<<1, 256>>>();
    bprob_kernel<<<(VV * (KT / 4) + 255) / 256, 256>>>();

    float* Tptr = nullptr;
    cudaGetSymbolAddress((void**)&Tptr, g_T);
    forward_kernel<<<FW_CTAS, 256>>>(words, Tptr, out);
}

// round 9
// speedup vs baseline: 8.5311x; 2.9380x over previous
#include <cuda_runtime.h>
#include <cuda_bf16.h>
#include <cstdint>
#include <math.h>

#define KT    64
#define VV    50000
#define DD    128
#define BOS_T 62
#define EOS_T 63
#define NB    8192
#define LL    126

#define EPS_F __uint_as_float(1u)
#define LOGV_F   10.819778284410284f
#define CORR_F   1363.2920638356958f

// Scratch (no allocation allowed)
__device__ float g_A[KT * KT];               // transition probs, f32 [k][j]
__device__ float g_T[VV * KT];               // logits (f32)
__device__ __nv_bfloat16 g_Tb[VV * KT];      // V-scaled emissions, bf16 [w][k]
__device__ float g_Z[KT];
#define ZBLK 128
__device__ float g_pm[ZBLK * KT];
__device__ float g_ps[ZBLK * KT];

// ---------------------------------------------------------------------------
// helpers
// ---------------------------------------------------------------------------
__device__ __forceinline__ void fma2(unsigned long long& d,
                                     unsigned long long a,
                                     unsigned long long b) {
    asm("fma.rn.f32x2 %0, %1, %2, %0;" : "+l"(d) : "l"(a), "l"(b));
}
__device__ __forceinline__ float lo64(unsigned long long v) {
    return __uint_as_float((unsigned)(v & 0xffffffffull));
}
__device__ __forceinline__ float hi64(unsigned long long v) {
    return __uint_as_float((unsigned)(v >> 32));
}
// pack two f32 -> bf16x2 reg {lo: l, hi: h}
__device__ __forceinline__ uint32_t pack_bf2(float l, float h) {
    uint32_t r;
    asm("cvt.rn.bf16x2.f32 %0, %1, %2;" : "=r"(r) : "f"(h), "f"(l));
    return r;
}
__device__ __forceinline__ float blo(uint32_t e) {
    return __uint_as_float(e << 16);
}
__device__ __forceinline__ float bhi(uint32_t e) {
    return __uint_as_float(e & 0xffff0000u);
}

// D[m16,n8] += A[m16,k16] * B[k16,n8], bf16 in, f32 accum
__device__ __forceinline__ void mma16816(float* c, const uint32_t* a,
                                         const uint32_t* b) {
    asm volatile(
        "mma.sync.aligned.m16n8k16.row.col.f32.bf16.bf16.f32 "
        "{%0,%1,%2,%3}, {%4,%5,%6,%7}, {%8,%9}, {%0,%1,%2,%3};"
        : "+f"(c[0]), "+f"(c[1]), "+f"(c[2]), "+f"(c[3])
        : "r"(a[0]), "r"(a[1]), "r"(a[2]), "r"(a[3]), "r"(b[0]), "r"(b[1]));
}

// ---------------------------------------------------------------------------
// Kernel 1: A = softmax(WA, BOS col -> -inf) + EPS, f32 row-major
// ---------------------------------------------------------------------------
__global__ void prep_A_kernel(const float* __restrict__ WA) {
    int k = threadIdx.x;
    if (k >= KT) return;
    float x[KT];
    float m = -INFINITY;
    #pragma unroll
    for (int j = 0; j < KT; j++) {
        float v = WA[k * KT + j];
        if (j == BOS_T) v = -INFINITY;
        x[j] = v;
        m = fmaxf(m, v);
    }
    float s = 0.f;
    #pragma unroll
    for (int j = 0; j < KT; j++) {
        float e = (j == BOS_T) ? 0.f : __expf(x[j] - m);
        x[j] = e;
        s += e;
    }
    float inv = 1.0f / s;
    #pragma unroll
    for (int j = 0; j < KT; j++)
        g_A[k * KT + j] = x[j] * inv + EPS_F;
}

// ---------------------------------------------------------------------------
// Kernel 2: raw logits  g_T[w*64+k] = dot(ThetaB[k], E[w])
// ---------------------------------------------------------------------------
#define WPB 16
#define TB_STRIDE 132

__global__ void __launch_bounds__(256) logits_kernel(const float* __restrict__ ThetaB,
                                                     const float* __restrict__ E) {
    __shared__ __align__(16) float Tbs[KT * TB_STRIDE];
    __shared__ __align__(16) float Es[WPB * DD];

    int tid = threadIdx.x;
    int wbase = blockIdx.x * WPB;

    for (int idx = tid; idx < KT * DD; idx += 256) {
        int k = idx >> 7, d = idx & 127;
        Tbs[k * TB_STRIDE + d] = ThetaB[idx];
    }
    for (int idx = tid; idx < WPB * DD; idx += 256)
        Es[idx] = E[(size_t)wbase * DD + idx];
    __syncthreads();

    int k  = tid & 63;
    int ws = tid >> 6;
    unsigned long long a0 = 0, a1 = 0, a2 = 0, a3 = 0;
    #pragma unroll 8
    for (int d = 0; d < DD; d += 4) {
        ulonglong2 tb = *reinterpret_cast<const ulonglong2*>(&Tbs[k * TB_STRIDE + d]);
        ulonglong2 e0 = *reinterpret_cast<const ulonglong2*>(&Es[(ws + 0) * DD + d]);
        ulonglong2 e1 = *reinterpret_cast<const ulonglong2*>(&Es[(ws + 4) * DD + d]);
        ulonglong2 e2 = *reinterpret_cast<const ulonglong2*>(&Es[(ws + 8) * DD + d]);
        ulonglong2 e3 = *reinterpret_cast<const ulonglong2*>(&Es[(ws + 12) * DD + d]);
        fma2(a0, tb.x, e0.x); fma2(a0, tb.y, e0.y);
        fma2(a1, tb.x, e1.x); fma2(a1, tb.y, e1.y);
        fma2(a2, tb.x, e2.x); fma2(a2, tb.y, e2.y);
        fma2(a3, tb.x, e3.x); fma2(a3, tb.y, e3.y);
    }
    g_T[(size_t)(wbase + ws + 0)  * KT + k] = lo64(a0) + hi64(a0);
    g_T[(size_t)(wbase + ws + 4)  * KT + k] = lo64(a1) + hi64(a1);
    g_T[(size_t)(wbase + ws + 8)  * KT + k] = lo64(a2) + hi64(a2);
    g_T[(size_t)(wbase + ws + 12) * KT + k] = lo64(a3) + hi64(a3);
}

// ---------------------------------------------------------------------------
// Kernel 3a: partial logsumexp per tag over row blocks
// ---------------------------------------------------------------------------
__global__ void __launch_bounds__(256) zred1_kernel() {
    int r0 = (int)(((long long)blockIdx.x * VV) / ZBLK);
    int r1 = (int)(((long long)(blockIdx.x + 1) * VV) / ZBLK);
    int tid = threadIdx.x;
    int k = tid & 63, g = tid >> 6;
    float m = -1e30f, s = 0.f;
    for (int r = r0 + g; r < r1; r += 4) {
        float x = g_T[(size_t)r * KT + k];
        if (x > m) { s = s * __expf(m - x) + 1.0f; m = x; }
        else       { s += __expf(x - m); }
    }
    __shared__ float sm[256], ss[256];
    sm[tid] = m; ss[tid] = s;
    __syncthreads();
    if (g == 0) {
        #pragma unroll
        for (int o = 1; o < 4; o++) {
            float m2 = sm[tid + o * 64], s2 = ss[tid + o * 64];
            if (m2 > m) { s = s * __expf(m - m2) + s2; m = m2; }
            else        { s += s2 * __expf(m2 - m); }
        }
        g_pm[blockIdx.x * KT + k] = m;
        g_ps[blockIdx.x * KT + k] = s;
    }
}

// Kernel 3b: one block per tag, tree reduce; folds -log(V) into Z
__global__ void __launch_bounds__(128) zred2_kernel() {
    int k = blockIdx.x;
    int tid = threadIdx.x;
    __shared__ float sm[128], ss[128];
    sm[tid] = g_pm[tid * KT + k];
    ss[tid] = g_ps[tid * KT + k];
    __syncthreads();
    for (int off = 64; off > 0; off >>= 1) {
        if (tid < off) {
            float m1 = sm[tid], s1 = ss[tid];
            float m2 = sm[tid + off], s2 = ss[tid + off];
            float M = fmaxf(m1, m2);
            sm[tid] = M;
            ss[tid] = s1 * __expf(m1 - M) + s2 * __expf(m2 - M);
        }
        __syncthreads();
    }
    if (tid == 0) g_Z[k] = sm[0] + __logf(ss[0]) - LOGV_F;
}

// ---------------------------------------------------------------------------
// Kernel 4: g_Tb[w][k] = bf16(exp(logit - Z'_k)) = V*B; 0 for BOS/EOS
// ---------------------------------------------------------------------------
__global__ void __launch_bounds__(256) bprob_kernel() {
    __shared__ float Zs[KT];
    if (threadIdx.x < KT) Zs[threadIdx.x] = g_Z[threadIdx.x];
    __syncthreads();
    size_t q = (size_t)blockIdx.x * 256 + threadIdx.x;
    if (q >= (size_t)VV * (KT / 4)) return;
    int k0 = (int)((q * 4) & 63);
    float4 v = *reinterpret_cast<const float4*>(&g_T[q * 4]);
    float r0, r1, r2, r3;
    if (k0 == 60) {
        r0 = __expf(v.x - Zs[60]);
        r1 = __expf(v.y - Zs[61]);
        r2 = 0.f;
        r3 = 0.f;
    } else {
        r0 = __expf(v.x - Zs[k0 + 0]);
        r1 = __expf(v.y - Zs[k0 + 1]);
        r2 = __expf(v.z - Zs[k0 + 2]);
        r3 = __expf(v.w - Zs[k0 + 3]);
    }
    uint2 st;
    st.x = pack_bf2(r0, r1);
    st.y = pack_bf2(r2, r3);
    reinterpret_cast<uint2*>(g_Tb)[q] = st;
}

// ---------------------------------------------------------------------------
// Kernel 5: mma.sync forward recursion. One warp = 16 sentences.
// alpha lives in m16k16 A-fragments (bf16); A_hmm in B-fragments (regs, once);
// D n-chunk pair == next A k-chunk fragment layout => pure register recursion.
// ---------------------------------------------------------------------------
__global__ void __launch_bounds__(64) forward_mma_kernel(const int* __restrict__ words,
                                                         float* __restrict__ out) {
    int tid  = threadIdx.x;
    int warp = tid >> 5;
    int lane = tid & 31;
    int g = lane >> 2;        // row group: owns rows g, g+8
    int t = lane & 3;         // col/k group

    int base = (blockIdx.x * 2 + warp) * 16;   // 16 sentences per warp

    // --- B fragments: Bf[nc][kc][2]; b holds A_hmm[k][n] col-major frag ---
    uint32_t Bf[8][4][2];
    #pragma unroll
    for (int nc = 0; nc < 8; nc++) {
        int n = 8 * nc + g;
        #pragma unroll
        for (int kc = 0; kc < 4; kc++) {
            int k0 = 16 * kc + 2 * t;
            Bf[nc][kc][0] = pack_bf2(g_A[(k0 + 0) * KT + n], g_A[(k0 + 1) * KT + n]);
            Bf[nc][kc][1] = pack_bf2(g_A[(k0 + 8) * KT + n], g_A[(k0 + 9) * KT + n]);
        }
    }

    // --- alpha fragments: af[kc][4]; init one-hot at k=62 ---
    uint32_t af[4][4];
    #pragma unroll
    for (int kc = 0; kc < 4; kc++)
        #pragma unroll
        for (int i = 0; i < 4; i++) af[kc][i] = 0u;
    if (t == 3) {                         // k pair {62,63} = kc3, a2/a3
        af[3][2] = 0x00003F80u;           // {lo:1.0bf16, hi:0}
        af[3][3] = 0x00003F80u;
    }

    const int* wpg = words + (size_t)(base + g) * LL;
    const int* wph = words + (size_t)(base + g + 8) * LL;

    // emission regs for current step (rows g / g+8), prefetched
    uint32_t eg[8], eh[8];
    int wg = wpg[0], wh = wph[0];
    #pragma unroll
    for (int nc = 0; nc < 8; nc++) {
        eg[nc] = *reinterpret_cast<const uint32_t*>(g_Tb + (size_t)wg * KT + 8 * nc + 2 * t);
        eh[nc] = *reinterpret_cast<const uint32_t*>(g_Tb + (size_t)wh * KT + 8 * nc + 2 * t);
    }
    int wg1 = wpg[1], wh1 = wph[1];

    float lsc0 = 0.f, lsc1 = 0.f;

    for (int step = 0; step < LL; step++) {
        // prefetch next emissions + word after
        uint32_t egn[8], ehn[8];
        #pragma unroll
        for (int nc = 0; nc < 8; nc++) {
            egn[nc] = *reinterpret_cast<const uint32_t*>(g_Tb + (size_t)wg1 * KT + 8 * nc + 2 * t);
            ehn[nc] = *reinterpret_cast<const uint32_t*>(g_Tb + (size_t)wh1 * KT + 8 * nc + 2 * t);
        }
        int nx = (step + 2 < LL) ? step + 2 : 0;
        int wg2 = wpg[nx], wh2 = wph[nx];

        // D = alpha @ A_hmm : 8 n-chunks, 4 k-chunks each
        float c[8][4];
        #pragma unroll
        for (int nc = 0; nc < 8; nc++) {
            c[nc][0] = 0.f; c[nc][1] = 0.f; c[nc][2] = 0.f; c[nc][3] = 0.f;
            #pragma unroll
            for (int kc = 0; kc < 4; kc++)
                mma16816(c[nc], af[kc], Bf[nc][kc]);
        }

        // multiply by emissions (fp32)
        float p[8][4];
        #pragma unroll
        for (int nc = 0; nc < 8; nc++) {
            p[nc][0] = c[nc][0] * blo(eg[nc]);
            p[nc][1] = c[nc][1] * bhi(eg[nc]);
            p[nc][2] = c[nc][2] * blo(eh[nc]);
            p[nc][3] = c[nc][3] * bhi(eh[nc]);
        }

        if ((step & 15) == 15) {
            // per-row rescale: rows g (p0,p1) and g+8 (p2,p3)
            float m0 = p[0][0], m1 = p[0][2];
            #pragma unroll
            for (int nc = 0; nc < 8; nc++) {
                m0 = fmaxf(m0, fmaxf(p[nc][0], p[nc][1]));
                m1 = fmaxf(m1, fmaxf(p[nc][2], p[nc][3]));
            }
            m0 = fmaxf(m0, __shfl_xor_sync(0xffffffffu, m0, 1));
            m0 = fmaxf(m0, __shfl_xor_sync(0xffffffffu, m0, 2));
            m1 = fmaxf(m1, __shfl_xor_sync(0xffffffffu, m1, 1));
            m1 = fmaxf(m1, __shfl_xor_sync(0xffffffffu, m1, 2));
            float r0 = __fdividef(1.0f, m0);
            float r1 = __fdividef(1.0f, m1);
            lsc0 += __logf(m0);
            lsc1 += __logf(m1);
            #pragma unroll
            for (int nc = 0; nc < 8; nc++) {
                p[nc][0] *= r0; p[nc][1] *= r0;
                p[nc][2] *= r1; p[nc][3] *= r1;
            }
        }

        // repack into next alpha fragments: nc pair (2kc, 2kc+1) -> kc
        #pragma unroll
        for (int kc = 0; kc < 4; kc++) {
            af[kc][0] = pack_bf2(p[2 * kc][0],     p[2 * kc][1]);
            af[kc][1] = pack_bf2(p[2 * kc][2],     p[2 * kc][3]);
            af[kc][2] = pack_bf2(p[2 * kc + 1][0], p[2 * kc + 1][1]);
            af[kc][3] = pack_bf2(p[2 * kc + 1][2], p[2 * kc + 1][3]);
        }

        #pragma unroll
        for (int nc = 0; nc < 8; nc++) { eg[nc] = egn[nc]; eh[nc] = ehn[nc]; }
        wg1 = wg2; wh1 = wh2;
    }

    // final transition into EOS: only n-chunk 7 (col 63 = 2t+1 at t==3)
    float cz[4] = {0.f, 0.f, 0.f, 0.f};
    #pragma unroll
    for (int kc = 0; kc < 4; kc++)
        mma16816(cz, af[kc], Bf[7][kc]);

    if (t == 3) {
        out[base + g]     = lsc0 + __logf(cz[1]) - CORR_F;
        out[base + g + 8] = lsc1 + __logf(cz[3]) - CORR_F;
    }
}

// ---------------------------------------------------------------------------
// Launch
// ---------------------------------------------------------------------------
extern "C" void kernel_launch(void* const* d_in, const int* in_sizes, int n_in,
                              void* d_out, int out_size) {
    const int*   words  = nullptr;
    const float* ThetaB = nullptr;
    const float* WA     = nullptr;
    const float* E      = nullptr;
    for (int i = 0; i < n_in; i++) {
        switch (in_sizes[i]) {
            case NB * LL:  words  = (const int*)d_in[i];   break;
            case KT * DD:  ThetaB = (const float*)d_in[i]; break;
            case KT * KT:  WA     = (const float*)d_in[i]; break;
            case VV * DD:  E      = (const float*)d_in[i]; break;
            default: break;
        }
    }
    float* out = (float*)d_out;

    prep_A_kernel<<<1, 64>>>(WA);
    logits_kernel<<<VV / WPB, 256>>>(ThetaB, E);
    zred1_kernel<<<ZBLK, 256>>>();
    zred2_kernel<<<KT, 128>>>();
    bprob_kernel<<<(VV * (KT / 4) + 255) / 256, 256>>>();
    forward_mma_kernel<<<NB / 32, 64>>>(words, out);
}

// round 10
// speedup vs baseline: 9.8990x; 1.1603x over previous
#include <cuda_runtime.h>
#include <cuda_bf16.h>
#include <cstdint>
#include <math.h>

#define KT    64
#define VV    50000
#define DD    128
#define BOS_T 62
#define EOS_T 63
#define NB    8192
#define LL    126

#define EPS_F __uint_as_float(1u)
#define CORR_F   1363.2920638356958f   // 126 * log(50000)

// Scratch (no allocation allowed)
__device__ float g_A[KT * KT];                       // transition probs, f32 [k][j]
__device__ float g_T[VV * KT];                       // exp(logit) table (f32)
__device__ __align__(128) __nv_bfloat16 g_Tb[VV * KT];  // permuted bf16 emissions
__device__ float g_S[KT];                            // per-tag scale V/sum
#define ZBLK 128
__device__ float g_ps[ZBLK * KT];                    // partial sums

// ---------------------------------------------------------------------------
// helpers
// ---------------------------------------------------------------------------
__device__ __forceinline__ void fma2(unsigned long long& d,
                                     unsigned long long a,
                                     unsigned long long b) {
    asm("fma.rn.f32x2 %0, %1, %2, %0;" : "+l"(d) : "l"(a), "l"(b));
}
__device__ __forceinline__ float lo64(unsigned long long v) {
    return __uint_as_float((unsigned)(v & 0xffffffffull));
}
__device__ __forceinline__ float hi64(unsigned long long v) {
    return __uint_as_float((unsigned)(v >> 32));
}
__device__ __forceinline__ uint32_t pack_bf2(float l, float h) {
    uint32_t r;
    asm("cvt.rn.bf16x2.f32 %0, %1, %2;" : "=r"(r) : "f"(h), "f"(l));
    return r;
}
__device__ __forceinline__ uint32_t mulbf2(uint32_t a, uint32_t b) {
    uint32_t r;
    asm("mul.bf16x2 %0, %1, %2;" : "=r"(r) : "r"(a), "r"(b));
    return r;
}
__device__ __forceinline__ float blo(uint32_t e) {
    return __uint_as_float(e << 16);
}
__device__ __forceinline__ float bhi(uint32_t e) {
    return __uint_as_float(e & 0xffff0000u);
}

// D[m16,n8] += A[m16,k16] * B[k16,n8], bf16 in, f32 accum
__device__ __forceinline__ void mma16816(float* c, const uint32_t* a,
                                         const uint32_t* b) {
    asm volatile(
        "mma.sync.aligned.m16n8k16.row.col.f32.bf16.bf16.f32 "
        "{%0,%1,%2,%3}, {%4,%5,%6,%7}, {%8,%9}, {%0,%1,%2,%3};"
        : "+f"(c[0]), "+f"(c[1]), "+f"(c[2]), "+f"(c[3])
        : "r"(a[0]), "r"(a[1]), "r"(a[2]), "r"(a[3]), "r"(b[0]), "r"(b[1]));
}

// ---------------------------------------------------------------------------
// Kernel 1: A = softmax(WA, BOS col -> -inf) + EPS, f32 row-major
// ---------------------------------------------------------------------------
__global__ void prep_A_kernel(const float* __restrict__ WA) {
    int k = threadIdx.x;
    if (k >= KT) return;
    float x[KT];
    float m = -INFINITY;
    #pragma unroll
    for (int j = 0; j < KT; j++) {
        float v = WA[k * KT + j];
        if (j == BOS_T) v = -INFINITY;
        x[j] = v;
        m = fmaxf(m, v);
    }
    float s = 0.f;
    #pragma unroll
    for (int j = 0; j < KT; j++) {
        float e = (j == BOS_T) ? 0.f : __expf(x[j] - m);
        x[j] = e;
        s += e;
    }
    float inv = 1.0f / s;
    #pragma unroll
    for (int j = 0; j < KT; j++)
        g_A[k * KT + j] = x[j] * inv + EPS_F;
}

// ---------------------------------------------------------------------------
// Kernel 2: g_T[w*64+k] = exp(dot(ThetaB[k], E[w]))   (no max shift needed:
// logits are O(0.1) by construction, exp is safe; MUFU hides under FFMA)
// ---------------------------------------------------------------------------
#define WPB 16
#define TB_STRIDE 132

__global__ void __launch_bounds__(256) logits_kernel(const float* __restrict__ ThetaB,
                                                     const float* __restrict__ E) {
    __shared__ __align__(16) float Tbs[KT * TB_STRIDE];
    __shared__ __align__(16) float Es[WPB * DD];

    int tid = threadIdx.x;
    int wbase = blockIdx.x * WPB;

    for (int idx = tid; idx < KT * DD; idx += 256) {
        int k = idx >> 7, d = idx & 127;
        Tbs[k * TB_STRIDE + d] = ThetaB[idx];
    }
    for (int idx = tid; idx < WPB * DD; idx += 256)
        Es[idx] = E[(size_t)wbase * DD + idx];
    __syncthreads();

    int k  = tid & 63;
    int ws = tid >> 6;
    unsigned long long a0 = 0, a1 = 0, a2 = 0, a3 = 0;
    #pragma unroll 8
    for (int d = 0; d < DD; d += 4) {
        ulonglong2 tb = *reinterpret_cast<const ulonglong2*>(&Tbs[k * TB_STRIDE + d]);
        ulonglong2 e0 = *reinterpret_cast<const ulonglong2*>(&Es[(ws + 0) * DD + d]);
        ulonglong2 e1 = *reinterpret_cast<const ulonglong2*>(&Es[(ws + 4) * DD + d]);
        ulonglong2 e2 = *reinterpret_cast<const ulonglong2*>(&Es[(ws + 8) * DD + d]);
        ulonglong2 e3 = *reinterpret_cast<const ulonglong2*>(&Es[(ws + 12) * DD + d]);
        fma2(a0, tb.x, e0.x); fma2(a0, tb.y, e0.y);
        fma2(a1, tb.x, e1.x); fma2(a1, tb.y, e1.y);
        fma2(a2, tb.x, e2.x); fma2(a2, tb.y, e2.y);
        fma2(a3, tb.x, e3.x); fma2(a3, tb.y, e3.y);
    }
    g_T[(size_t)(wbase + ws + 0)  * KT + k] = __expf(lo64(a0) + hi64(a0));
    g_T[(size_t)(wbase + ws + 4)  * KT + k] = __expf(lo64(a1) + hi64(a1));
    g_T[(size_t)(wbase + ws + 8)  * KT + k] = __expf(lo64(a2) + hi64(a2));
    g_T[(size_t)(wbase + ws + 12) * KT + k] = __expf(lo64(a3) + hi64(a3));
}

// ---------------------------------------------------------------------------
// Kernel 3a: partial column sums of exp table (pure FADD, memory-bound)
// ---------------------------------------------------------------------------
__global__ void __launch_bounds__(256) zred1_kernel() {
    int r0 = (int)(((long long)blockIdx.x * VV) / ZBLK);
    int r1 = (int)(((long long)(blockIdx.x + 1) * VV) / ZBLK);
    int tid = threadIdx.x;
    int k = tid & 63, g = tid >> 6;
    float s = 0.f;
    for (int r = r0 + g; r < r1; r += 4)
        s += g_T[(size_t)r * KT + k];
    __shared__ float ss[256];
    ss[tid] = s;
    __syncthreads();
    if (g == 0) {
        s += ss[tid + 64] + ss[tid + 128] + ss[tid + 192];
        g_ps[blockIdx.x * KT + k] = s;
    }
}

// Kernel 3b: reduce partials -> g_S[k] = V / sum_k
__global__ void __launch_bounds__(256) zred2_kernel() {
    int tid = threadIdx.x;
    int k = tid & 63, g = tid >> 6;
    float s = 0.f;
    for (int b = g; b < ZBLK; b += 4)
        s += g_ps[b * KT + k];
    __shared__ float ss[256];
    ss[tid] = s;
    __syncthreads();
    if (g == 0) {
        s += ss[tid + 64] + ss[tid + 128] + ss[tid + 192];
        g_S[k] = (float)VV / s;   // em = exp(logit) * V/sum = V*B
    }
}

// ---------------------------------------------------------------------------
// Kernel 4: permuted bf16 emission table.
// Permutation per word-row: u32 slot (t*8 + nc) holds cols (8nc+2t, 8nc+2t+1),
// so forward thread t reads its 16 values as two uint4. Cols 62,63 -> 0.
// ---------------------------------------------------------------------------
__global__ void __launch_bounds__(256) bprob_kernel() {
    __shared__ float Ss[KT];
    if (threadIdx.x < KT) Ss[threadIdx.x] = g_S[threadIdx.x];
    __syncthreads();
    int idx = blockIdx.x * 256 + threadIdx.x;
    if (idx >= VV * 4) return;
    int w = idx >> 2, t = idx & 3;
    const float2* row = reinterpret_cast<const float2*>(g_T + (size_t)w * KT);
    unsigned u[8];
    #pragma unroll
    for (int nc = 0; nc < 8; nc++) {
        float2 v = row[4 * nc + t];
        int c = 8 * nc + 2 * t;
        float a = v.x * Ss[c];
        float b = v.y * Ss[c + 1];
        if (t == 3 && nc == 7) { a = 0.f; b = 0.f; }   // BOS/EOS cols 62,63
        u[nc] = pack_bf2(a, b);
    }
    uint4* dst = reinterpret_cast<uint4*>(g_Tb) + (size_t)w * 8 + t * 2;
    dst[0] = make_uint4(u[0], u[1], u[2], u[3]);
    dst[1] = make_uint4(u[4], u[5], u[6], u[7]);
}

// ---------------------------------------------------------------------------
// Kernel 5: mma.sync forward recursion. One warp = 16 sentences.
// Emissions: 4x LDG.128/thread/step from the permuted table (prefetched).
// Fast path: cvt D->bf16x2, mul.bf16x2 -> next A fragment directly.
// ---------------------------------------------------------------------------
__global__ void __launch_bounds__(64) forward_mma_kernel(const int* __restrict__ words,
                                                         float* __restrict__ out) {
    int tid  = threadIdx.x;
    int warp = tid >> 5;
    int lane = tid & 31;
    int g = lane >> 2;        // row group: owns rows g, g+8
    int t = lane & 3;         // col/k group

    int base = (blockIdx.x * 2 + warp) * 16;

    // B fragments of A_hmm (col-major): Bf[nc][kc][2]
    uint32_t Bf[8][4][2];
    #pragma unroll
    for (int nc = 0; nc < 8; nc++) {
        int n = 8 * nc + g;
        #pragma unroll
        for (int kc = 0; kc < 4; kc++) {
            int k0 = 16 * kc + 2 * t;
            Bf[nc][kc][0] = pack_bf2(g_A[(k0 + 0) * KT + n], g_A[(k0 + 1) * KT + n]);
            Bf[nc][kc][1] = pack_bf2(g_A[(k0 + 8) * KT + n], g_A[(k0 + 9) * KT + n]);
        }
    }

    // alpha fragments: one-hot at k=62
    uint32_t af[4][4];
    #pragma unroll
    for (int kc = 0; kc < 4; kc++)
        #pragma unroll
        for (int i = 0; i < 4; i++) af[kc][i] = 0u;
    if (t == 3) {
        af[3][2] = 0x00003F80u;
        af[3][3] = 0x00003F80u;
    }

    const int* wpg = words + (size_t)(base + g) * LL;
    const int* wph = words + (size_t)(base + g + 8) * LL;

    const uint4* Tb4 = reinterpret_cast<const uint4*>(g_Tb);

    uint32_t eg[8], eh[8];
    {
        int wg = wpg[0], wh = wph[0];
        uint4 ga = Tb4[(size_t)wg * 8 + t * 2], gb = Tb4[(size_t)wg * 8 + t * 2 + 1];
        uint4 ha = Tb4[(size_t)wh * 8 + t * 2], hb = Tb4[(size_t)wh * 8 + t * 2 + 1];
        eg[0] = ga.x; eg[1] = ga.y; eg[2] = ga.z; eg[3] = ga.w;
        eg[4] = gb.x; eg[5] = gb.y; eg[6] = gb.z; eg[7] = gb.w;
        eh[0] = ha.x; eh[1] = ha.y; eh[2] = ha.z; eh[3] = ha.w;
        eh[4] = hb.x; eh[5] = hb.y; eh[6] = hb.z; eh[7] = hb.w;
    }
    int wg1 = wpg[1], wh1 = wph[1];

    float lsc0 = 0.f, lsc1 = 0.f;

    for (int step = 0; step < LL; step++) {
        // prefetch next emissions + word after
        uint4 ga = Tb4[(size_t)wg1 * 8 + t * 2], gb = Tb4[(size_t)wg1 * 8 + t * 2 + 1];
        uint4 ha = Tb4[(size_t)wh1 * 8 + t * 2], hb = Tb4[(size_t)wh1 * 8 + t * 2 + 1];
        int nx = (step + 2 < LL) ? step + 2 : 0;
        int wg2 = wpg[nx], wh2 = wph[nx];

        // D = alpha @ A_hmm
        float c[8][4];
        #pragma unroll
        for (int nc = 0; nc < 8; nc++) {
            c[nc][0] = 0.f; c[nc][1] = 0.f; c[nc][2] = 0.f; c[nc][3] = 0.f;
            #pragma unroll
            for (int kc = 0; kc < 4; kc++)
                mma16816(c[nc], af[kc], Bf[nc][kc]);
        }

        uint32_t og[8], oh[8];
        if ((step & 15) == 15) {
            // rescale path: f32 emission multiply, per-row max, normalize
            float p[8][4];
            float m0 = -1.f, m1 = -1.f;
            #pragma unroll
            for (int nc = 0; nc < 8; nc++) {
                p[nc][0] = c[nc][0] * blo(eg[nc]);
                p[nc][1] = c[nc][1] * bhi(eg[nc]);
                p[nc][2] = c[nc][2] * blo(eh[nc]);
                p[nc][3] = c[nc][3] * bhi(eh[nc]);
                m0 = fmaxf(m0, fmaxf(p[nc][0], p[nc][1]));
                m1 = fmaxf(m1, fmaxf(p[nc][2], p[nc][3]));
            }
            m0 = fmaxf(m0, __shfl_xor_sync(0xffffffffu, m0, 1));
            m0 = fmaxf(m0, __shfl_xor_sync(0xffffffffu, m0, 2));
            m1 = fmaxf(m1, __shfl_xor_sync(0xffffffffu, m1, 1));
            m1 = fmaxf(m1, __shfl_xor_sync(0xffffffffu, m1, 2));
            float r0 = __fdividef(1.0f, m0);
            float r1 = __fdividef(1.0f, m1);
            lsc0 += __logf(m0);
            lsc1 += __logf(m1);
            #pragma unroll
            for (int nc = 0; nc < 8; nc++) {
                og[nc] = pack_bf2(p[nc][0] * r0, p[nc][1] * r0);
                oh[nc] = pack_bf2(p[nc][2] * r1, p[nc][3] * r1);
            }
        } else {
            // fast path: cvt + packed bf16 multiply -> next fragment directly
            #pragma unroll
            for (int nc = 0; nc < 8; nc++) {
                og[nc] = mulbf2(pack_bf2(c[nc][0], c[nc][1]), eg[nc]);
                oh[nc] = mulbf2(pack_bf2(c[nc][2], c[nc][3]), eh[nc]);
            }
        }

        // D n-chunk pair -> next A k-chunk fragment
        #pragma unroll
        for (int kc = 0; kc < 4; kc++) {
            af[kc][0] = og[2 * kc];
            af[kc][1] = oh[2 * kc];
            af[kc][2] = og[2 * kc + 1];
            af[kc][3] = oh[2 * kc + 1];
        }

        eg[0] = ga.x; eg[1] = ga.y; eg[2] = ga.z; eg[3] = ga.w;
        eg[4] = gb.x; eg[5] = gb.y; eg[6] = gb.z; eg[7] = gb.w;
        eh[0] = ha.x; eh[1] = ha.y; eh[2] = ha.z; eh[3] = ha.w;
        eh[4] = hb.x; eh[5] = hb.y; eh[6] = hb.z; eh[7] = hb.w;
        wg1 = wg2; wh1 = wh2;
    }

    // final transition into EOS: n-chunk 7 only (col 63 = lane t==3, c1/c3)
    float cz[4] = {0.f, 0.f, 0.f, 0.f};
    #pragma unroll
    for (int kc = 0; kc < 4; kc++)
        mma16816(cz, af[kc], Bf[7][kc]);

    if (t == 3) {
        out[base + g]     = lsc0 + __logf(cz[1]) - CORR_F;
        out[base + g + 8] = lsc1 + __logf(cz[3]) - CORR_F;
    }
}

// ---------------------------------------------------------------------------
// Launch
// ---------------------------------------------------------------------------
extern "C" void kernel_launch(void* const* d_in, const int* in_sizes, int n_in,
                              void* d_out, int out_size) {
    const int*   words  = nullptr;
    const float* ThetaB = nullptr;
    const float* WA     = nullptr;
    const float* E      = nullptr;
    for (int i = 0; i < n_in; i++) {
        switch (in_sizes[i]) {
            case NB * LL:  words  = (const int*)d_in[i];   break;
            case KT * DD:  ThetaB = (const float*)d_in[i]; break;
            case KT * KT:  WA     = (const float*)d_in[i]; break;
            case VV * DD:  E      = (const float*)d_in[i]; break;
            default: break;
        }
    }
    float* out = (float*)d_out;

    prep_A_kernel<<<1, 64>>>(WA);
    logits_kernel<<<VV / WPB, 256>>>(ThetaB, E);
    zred1_kernel<<<ZBLK, 256>>>();
    zred2_kernel<<<1, 256>>>();
    bprob_kernel<<<(VV * 4 + 255) / 256, 256>>>();
    forward_mma_kernel<<<NB / 32, 64>>>(words, out);
}